// round 13
// baseline (speedup 1.0000x reference)
#include <cuda_runtime.h>
#include <cuda_fp16.h>
#include <cstdint>

// Problem constants
#define BB 2
#define SS 4096
#define HH 512
#define GG 18
#define NHEAD 8
#define DD 64
#define GH (GG*HH)        // 9216
#define MTOK (BB*SS)      // 8192

// mma GEMM config: CTA 128x128, 4 warps (2m x 2n), warp tile 64x64, BKK=32
#define BKM 128
#define BKN 128
#define BKK 32
#define GROUPM 16
#define STAGES 4
#define NTHR 128
#define SMEM_STAGE 16384                 // A 8KB + B 8KB
#define SMEM_MAIN (STAGES*SMEM_STAGE)    // 65536
#define SMEM_CONN (128*GG*4)             // 9216
#define SMEM_G (SMEM_MAIN + SMEM_CONN)   // 74752

#define KV_TILES (2*(GH/BKN))            // 144
#define Q_TILES  (HH/BKN)                // 4

// ---------- static device scratch ----------
__device__ __half g_hidh[(size_t)MTOK * HH];   // hidden fp16 (16MB)
__device__ __half g_Wkh[(size_t)GH * GH];      // Wk fp16 [K,N] (170MB)
__device__ __half g_Wvh[(size_t)GH * GH];
__device__ __half g_Wqh[(size_t)HH * HH];
__device__ __half g_Woh[(size_t)HH * HH];
__device__ __half g_keyh[(size_t)MTOK * GH];   // 151MB fp16
__device__ __half g_valh[(size_t)MTOK * GH];   // 151MB fp16
__device__ __half g_qh[(size_t)MTOK * HH];
__device__ __half g_attnh[(size_t)MTOK * HH];
__device__ int    g_is64;

// ---------- helpers ----------
__device__ __forceinline__ uint32_t smem_u32(const void* p) {
    uint32_t a;
    asm("{ .reg .u64 t; cvta.to.shared.u64 t, %1; cvt.u32.u64 %0, t; }" : "=r"(a) : "l"(p));
    return a;
}
__device__ __forceinline__ void cp16(uint32_t saddr, const void* gptr) {
    asm volatile("cp.async.cg.shared.global [%0], [%1], 16;" :: "r"(saddr), "l"(gptr) : "memory");
}
__device__ __forceinline__ void cp16z(uint32_t saddr, const void* gptr, uint32_t srcsz) {
    asm volatile("cp.async.cg.shared.global [%0], [%1], 16, %2;"
                 :: "r"(saddr), "l"(gptr), "r"(srcsz) : "memory");
}
__device__ __forceinline__ void cp_commit() { asm volatile("cp.async.commit_group;" ::: "memory"); }
__device__ __forceinline__ void cp_wait2()  { asm volatile("cp.async.wait_group 2;" ::: "memory"); }

// A tile [128 m][32 k] halfs: row = 64B = 4 chunks of 16B (swizzled in 128B pairs)
__device__ __forceinline__ uint32_t swA(int r, int ch) {
    return (uint32_t)(r * 64 + ((ch ^ ((r >> 1) & 3)) << 4));
}
// B tile [32 k][128 n] halfs: row = 256B, 16 chunks of 16B, XOR-swizzled
__device__ __forceinline__ uint32_t swB(int k, int nch) {
    return (uint32_t)(k * 256 + ((nch ^ (k & 7)) << 4));
}
__device__ __forceinline__ void ldsm4(uint32_t* r, uint32_t addr) {
    asm volatile("ldmatrix.sync.aligned.m8n8.x4.shared.b16 {%0,%1,%2,%3}, [%4];"
                 : "=r"(r[0]), "=r"(r[1]), "=r"(r[2]), "=r"(r[3]) : "r"(addr));
}
__device__ __forceinline__ void ldsm4t(uint32_t& r0, uint32_t& r1, uint32_t& r2, uint32_t& r3,
                                       uint32_t addr) {
    asm volatile("ldmatrix.sync.aligned.m8n8.x4.trans.shared.b16 {%0,%1,%2,%3}, [%4];"
                 : "=r"(r0), "=r"(r1), "=r"(r2), "=r"(r3) : "r"(addr));
}
__device__ __forceinline__ void mma16816(float* d, const uint32_t* a, const uint32_t* b) {
    asm volatile(
        "mma.sync.aligned.m16n8k16.row.col.f32.f16.f16.f32 "
        "{%0,%1,%2,%3}, {%4,%5,%6,%7}, {%8,%9}, {%0,%1,%2,%3};"
        : "+f"(d[0]), "+f"(d[1]), "+f"(d[2]), "+f"(d[3])
        : "r"(a[0]), "r"(a[1]), "r"(a[2]), "r"(a[3]), "r"(b[0]), "r"(b[1]));
}

// ---------- detect int width of connections ----------
__global__ void detect_kernel(const int* __restrict__ conn) {
    if (threadIdx.x == 0 && blockIdx.x == 0) {
        int is64 = 1;
        #pragma unroll
        for (int i = 0; i < 64; i++) {
            if (conn[2 * i + 1] != 0) { is64 = 0; break; }
        }
        g_is64 = is64;
    }
}

// ---------- prep: convert all fp32 operands to fp16, 8 floats/thread ----------
#define H2  524288ull         // hidden float4-PAIRS
#define W2  10616832ull       // 9216*9216/8
#define S2  32768ull          // 512*512/8
__global__ void prep_kernel(const float4* __restrict__ hid, const float4* __restrict__ wk,
                            const float4* __restrict__ wv, const float4* __restrict__ wq,
                            const float4* __restrict__ wo,
                            uint4* __restrict__ hidh, uint4* __restrict__ wkh,
                            uint4* __restrict__ wvh, uint4* __restrict__ wqh,
                            uint4* __restrict__ woh) {
    size_t t = (size_t)blockIdx.x * blockDim.x + threadIdx.x;   // pair index
    const float4* src; uint4* dst; size_t p;
    if (t < H2)                       { src = hid; dst = hidh; p = t; }
    else if (t < H2 + W2)             { src = wk;  dst = wkh;  p = t - H2; }
    else if (t < H2 + 2*W2)           { src = wv;  dst = wvh;  p = t - H2 - W2; }
    else if (t < H2 + 2*W2 + S2)      { src = wq;  dst = wqh;  p = t - H2 - 2*W2; }
    else if (t < H2 + 2*W2 + 2*S2)    { src = wo;  dst = woh;  p = t - H2 - 2*W2 - S2; }
    else return;
    float4 v0 = src[2 * p];
    float4 v1 = src[2 * p + 1];
    union { __half2 h[4]; uint4 u; } pk;
    pk.h[0] = __floats2half2_rn(v0.x, v0.y);
    pk.h[1] = __floats2half2_rn(v0.z, v0.w);
    pk.h[2] = __floats2half2_rn(v1.x, v1.y);
    pk.h[3] = __floats2half2_rn(v1.z, v1.w);
    dst[p] = pk.u;
}

// ---------- fp16 tensor-core GEMM ----------
// C[M, Ntot] = A[M, Kdim] * B[Kdim, Ntot]   (B row-major K-major, ldmatrix.trans)
// GATHER: A row r of tile = hidden_h[b*SS + conn[token, g]], zeros if conn<0.
// HALF_OUT: write __half outputs; else fp32.
// Segments: n_id < n_split1 -> (B1,C1); < n_split2 -> (B2,C2);
// MERGEQ && n_id >= n_split2 -> (B3,C3) with NtotQ/nktQ and identity gather
// (Q-proj tiles backfill the KV launch's tail wave).
template<bool GATHER, bool HALF_OUT, bool MERGEQ>
__global__ __launch_bounds__(NTHR, 2)
void gemm_mma(const __half* __restrict__ Abase,
              const __half* __restrict__ B1, const __half* __restrict__ B2,
              const __half* __restrict__ B3,
              void* __restrict__ Cv1, void* __restrict__ Cv2, void* __restrict__ Cv3,
              const void* __restrict__ conn,
              int Kdim, int Ntot0, int n_tiles, int n_split1, int n_split2,
              int nkt0, int NtotQ, int nktQ) {
    extern __shared__ char smem[];
    uint32_t sbase = smem_u32(smem);
    int* sconn = (int*)(smem + SMEM_MAIN);
    int tid = threadIdx.x;
    int lane = tid & 31, w = tid >> 5;
    int wm = w >> 1, wn = w & 1;          // 2 (m) x 2 (n) warps, warp tile 64x64

    // grouped rasterization (n spans all segments -> A reuse in L2)
    int pid = blockIdx.x;
    int per_g = GROUPM * n_tiles;
    int g = pid / per_g;
    int rem = pid - g * per_g;
    int m_id = g * GROUPM + (rem % GROUPM);
    int n_id = rem / GROUPM;
    int tok0 = m_id * BKM;

    const __half* B;
    void* Cv;
    int n_loc;
    int Ntot = Ntot0, nkt = nkt0;
    bool isQ = false;
    if (n_id < n_split1)      { B = B1; Cv = Cv1; n_loc = n_id; }
    else if (n_id < n_split2) { B = B2; Cv = Cv2; n_loc = n_id - n_split1; }
    else                      { B = B3; Cv = Cv3; n_loc = n_id - n_split2;
                                Ntot = NtotQ; nkt = nktQ; isQ = true; }

    // preload + clip connection indices for this CTA's 128 tokens
    if (GATHER) {
        if (MERGEQ && isQ) {
            // identity gather: A row = the token itself (within its batch)
            for (int i = tid; i < BKM * GG; i += NTHR)
                sconn[i] = (tok0 + i / GG) & (SS - 1);
        } else {
            int is64 = g_is64;
            for (int i = tid; i < BKM * GG; i += NTHR) {
                size_t idx = (size_t)(tok0 + i / GG) * GG + (i % GG);
                long long c = is64 ? ((const long long*)conn)[idx]
                                   : (long long)((const int*)conn)[idx];
                sconn[i] = c < 0 ? -1 : (c > SS - 1 ? SS - 1 : (int)c);
            }
        }
        __syncthreads();
    }

    // per-thread load coordinates (4 A chunks + 4 B chunks per stage)
    int rA[4], chA[4]; uint32_t soA[4];
    uint32_t soB[4]; const __half* gB[4];
    #pragma unroll
    for (int i = 0; i < 4; i++) {
        int cA = tid + i * NTHR;          // 0..511
        rA[i] = cA >> 2; chA[i] = cA & 3;
        soA[i] = swA(rA[i], chA[i]);
        int cB = tid + i * NTHR;
        int krB = cB >> 4; int nch = cB & 15;
        soB[i] = swB(krB, nch);
        gB[i] = B + (size_t)krB * Ntot + (size_t)n_loc * BKN + nch * 8;
    }
    const __half* hidb = GATHER ? Abase + ((size_t)(tok0 >> 12) << 12) * HH : nullptr;

    #define LOAD_TILE(s, kt)                                                       \
    do {                                                                           \
        uint32_t sA_ = sbase + (s) * SMEM_STAGE;                                   \
        uint32_t sB_ = sA_ + 8192;                                                 \
        int kb_ = (kt) * BKK;                                                      \
        if (GATHER) {                                                              \
            int gg_ = kb_ >> 9;                                                    \
            int off_ = kb_ & 511;                                                  \
            _Pragma("unroll")                                                      \
            for (int i = 0; i < 4; i++) {                                          \
                int idx_ = sconn[rA[i] * GG + gg_];                                \
                int idc_ = idx_ < 0 ? 0 : idx_;                                    \
                cp16z(sA_ + soA[i],                                                \
                      hidb + (size_t)idc_ * HH + off_ + chA[i] * 8,                \
                      idx_ < 0 ? 0u : 16u);                                        \
            }                                                                      \
        } else {                                                                   \
            _Pragma("unroll")                                                      \
            for (int i = 0; i < 4; i++)                                            \
                cp16(sA_ + soA[i],                                                 \
                     Abase + (size_t)(tok0 + rA[i]) * Kdim + kb_ + chA[i] * 8);    \
        }                                                                          \
        _Pragma("unroll")                                                          \
        for (int i = 0; i < 4; i++)                                                \
            cp16(sB_ + soB[i], gB[i] + (size_t)kb_ * Ntot);                        \
    } while (0)

    LOAD_TILE(0, 0); cp_commit();
    LOAD_TILE(1, 1); cp_commit();
    LOAD_TILE(2, 2); cp_commit();

    float acc[4][8][4] = {};

    int a_row = ((lane >> 3) & 1) * 8 + (lane & 7) + wm * 64;  // + mf*16
    int a_chb = lane >> 4;                                     // + kf*2
    int b_krb = ((lane >> 3) & 1) * 8 + (lane & 7);            // + kf*16
    int b_nchb = wn * 8 + (lane >> 4);                         // + np*2

    for (int kt = 0; kt < nkt; kt++) {
        int s = kt & (STAGES - 1);
        cp_wait2();
        __syncthreads();
        uint32_t sA = sbase + s * SMEM_STAGE;
        uint32_t sB = sA + 8192;

        #pragma unroll
        for (int kf = 0; kf < 2; kf++) {
            uint32_t af[4][4];
            uint32_t bf[8][2];
            #pragma unroll
            for (int mf = 0; mf < 4; mf++)
                ldsm4(af[mf], sA + swA(a_row + mf * 16, a_chb + kf * 2));
            #pragma unroll
            for (int np = 0; np < 4; np++) {
                uint32_t q0, q1, q2, q3;
                ldsm4t(q0, q1, q2, q3, sB + swB(b_krb + kf * 16, b_nchb + np * 2));
                bf[np * 2][0] = q0;     bf[np * 2][1] = q1;
                bf[np * 2 + 1][0] = q2; bf[np * 2 + 1][1] = q3;
            }
            #pragma unroll
            for (int mf = 0; mf < 4; mf++)
                #pragma unroll
                for (int nf = 0; nf < 8; nf++)
                    mma16816(acc[mf][nf], af[mf], bf[nf]);
        }

        if (kt + 3 < nkt) LOAD_TILE((kt + 3) & (STAGES - 1), kt + 3);
        cp_commit();
    }
    #undef LOAD_TILE

    // epilogue
    size_t cm = (size_t)tok0 + wm * 64;
    size_t cn = (size_t)n_loc * BKN + wn * 64;
    #pragma unroll
    for (int mf = 0; mf < 4; mf++) {
        #pragma unroll
        for (int nf = 0; nf < 8; nf++) {
            size_t row = cm + mf * 16 + (lane >> 2);
            size_t col = cn + nf * 8 + (lane & 3) * 2;
            if (HALF_OUT) {
                __half* C = (__half*)Cv;
                *(__half2*)&C[row * Ntot + col] = __floats2half2_rn(acc[mf][nf][0], acc[mf][nf][1]);
                *(__half2*)&C[(row + 8) * Ntot + col] = __floats2half2_rn(acc[mf][nf][2], acc[mf][nf][3]);
            } else {
                float* C = (float*)Cv;
                *(float2*)&C[row * Ntot + col] = make_float2(acc[mf][nf][0], acc[mf][nf][1]);
                *(float2*)&C[(row + 8) * Ntot + col] = make_float2(acc[mf][nf][2], acc[mf][nf][3]);
            }
        }
    }
}

// ---------- attention over G=18 connections (fp16 in, fp16 out) ----------
__global__ __launch_bounds__(256)
void attn_kernel(const __half2* __restrict__ q, const __half2* __restrict__ key,
                 const __half2* __restrict__ val, __half2* __restrict__ outh) {
    int bs = blockIdx.x;
    int head = threadIdx.x >> 5;
    int lane = threadIdx.x & 31;

    float2 qv = __half22float2(q[((size_t)bs * HH + head * DD) / 2 + lane]);

    float sc[GG];
    const __half2* kb = key + ((size_t)bs * GH + head * DD) / 2 + lane;
    #pragma unroll
    for (int j = 0; j < GG; j++) {
        float2 kv = __half22float2(kb[(size_t)j * (HH / 2)]);
        float s = qv.x * kv.x + qv.y * kv.y;
        s += __shfl_xor_sync(0xFFFFFFFFu, s, 16);
        s += __shfl_xor_sync(0xFFFFFFFFu, s, 8);
        s += __shfl_xor_sync(0xFFFFFFFFu, s, 4);
        s += __shfl_xor_sync(0xFFFFFFFFu, s, 2);
        s += __shfl_xor_sync(0xFFFFFFFFu, s, 1);
        sc[j] = s * 0.125f;
    }
    float m = sc[0];
    #pragma unroll
    for (int j = 1; j < GG; j++) m = fmaxf(m, sc[j]);
    float sum = 0.f;
    #pragma unroll
    for (int j = 0; j < GG; j++) { sc[j] = __expf(sc[j] - m); sum += sc[j]; }
    float inv = 1.f / sum;

    float ox = 0.f, oy = 0.f;
    const __half2* vb = val + ((size_t)bs * GH + head * DD) / 2 + lane;
    #pragma unroll
    for (int j = 0; j < GG; j++) {
        float2 vv = __half22float2(vb[(size_t)j * (HH / 2)]);
        ox = fmaf(sc[j], vv.x, ox);
        oy = fmaf(sc[j], vv.y, oy);
    }
    outh[((size_t)bs * HH + head * DD) / 2 + lane] = __floats2half2_rn(ox * inv, oy * inv);
}

// ---------- launch ----------
extern "C" void kernel_launch(void* const* d_in, const int* in_sizes, int n_in,
                              void* d_out, int out_size) {
    const float* hidden = (const float*)d_in[0];
    const void*  conn   = d_in[1];
    const float* Wq     = (const float*)d_in[2];
    const float* Wk     = (const float*)d_in[3];
    const float* Wv     = (const float*)d_in[4];
    const float* Wo     = (const float*)d_in[5];
    float* out = (float*)d_out;

    __half *pHid, *pWkh, *pWvh, *pWqh, *pWoh, *pKeyh, *pValh, *pQh, *pAttnh;
    cudaGetSymbolAddress((void**)&pHid,   g_hidh);
    cudaGetSymbolAddress((void**)&pWkh,   g_Wkh);
    cudaGetSymbolAddress((void**)&pWvh,   g_Wvh);
    cudaGetSymbolAddress((void**)&pWqh,   g_Wqh);
    cudaGetSymbolAddress((void**)&pWoh,   g_Woh);
    cudaGetSymbolAddress((void**)&pKeyh,  g_keyh);
    cudaGetSymbolAddress((void**)&pValh,  g_valh);
    cudaGetSymbolAddress((void**)&pQh,    g_qh);
    cudaGetSymbolAddress((void**)&pAttnh, g_attnh);

    cudaFuncSetAttribute((const void*)gemm_mma<true, true, true>,
                         cudaFuncAttributeMaxDynamicSharedMemorySize, SMEM_G);
    cudaFuncSetAttribute((const void*)gemm_mma<false, false, false>,
                         cudaFuncAttributeMaxDynamicSharedMemorySize, SMEM_G);

    // 1) int width detection
    detect_kernel<<<1, 32>>>((const int*)conn);

    // 2) fp16 conversion of all operands (16B stores)
    {
        size_t total = H2 + 2 * W2 + 2 * S2;
        prep_kernel<<<(unsigned)((total + 255) / 256), 256>>>(
            (const float4*)hidden, (const float4*)Wk, (const float4*)Wv,
            (const float4*)Wq, (const float4*)Wo,
            (uint4*)pHid, (uint4*)pWkh, (uint4*)pWvh, (uint4*)pWqh, (uint4*)pWoh);
    }

    // 3) key+value+query in ONE launch: n tiles span Wk|Wv|Wq
    {
        int n_tiles = KV_TILES + Q_TILES;          // 148
        int grid = (MTOK / BKM) * n_tiles;         // 9472
        gemm_mma<true, true, true><<<grid, NTHR, SMEM_G>>>(
            pHid, pWkh, pWvh, pWqh, pKeyh, pValh, pQh, conn,
            GH, GH, n_tiles, GH / BKN, KV_TILES, GH / BKK, HH, HH / BKK);
    }

    // 4) attention (fp16 in/out)
    attn_kernel<<<MTOK, 256>>>((const __half2*)pQh, (const __half2*)pKeyh,
                               (const __half2*)pValh, (__half2*)pAttnh);

    // 5) out = attn @ Wo -> fp32
    gemm_mma<false, false, false><<<(MTOK / BKM) * (HH / BKN), NTHR, SMEM_G>>>(
        pAttnh, pWoh, pWoh, pWoh, out, out, out, nullptr,
        HH, HH, HH / BKN, HH / BKN, HH / BKN, HH / BKK, HH, HH / BKK);
}

// round 14
// speedup vs baseline: 1.0001x; 1.0001x over previous
#include <cuda_runtime.h>
#include <cuda_fp16.h>
#include <cstdint>

// Problem constants
#define BB 2
#define SS 4096
#define HH 512
#define GG 18
#define NHEAD 8
#define DD 64
#define GH (GG*HH)        // 9216
#define MTOK (BB*SS)      // 8192

// mma GEMM config: CTA 128x128, 4 warps (2m x 2n), warp tile 64x64, BKK=32
#define BKM 128
#define BKN 128
#define BKK 32
#define GROUPM 32
#define STAGES 4
#define NTHR 128
#define SMEM_STAGE 16384                 // A 8KB + B 8KB
#define SMEM_MAIN (STAGES*SMEM_STAGE)    // 65536
#define SMEM_CONN (128*GG*4)             // 9216
#define SMEM_G (SMEM_MAIN + SMEM_CONN)   // 74752

#define KV_TILES (2*(GH/BKN))            // 144
#define Q_TILES  (HH/BKN)                // 4

// ---------- static device scratch ----------
__device__ __half g_hidh[(size_t)MTOK * HH];   // hidden fp16 (16MB)
__device__ __half g_Wkh[(size_t)GH * GH];      // Wk fp16 [K,N] (170MB)
__device__ __half g_Wvh[(size_t)GH * GH];
__device__ __half g_Wqh[(size_t)HH * HH];
__device__ __half g_Woh[(size_t)HH * HH];
__device__ __half g_keyh[(size_t)MTOK * GH];   // 151MB fp16
__device__ __half g_valh[(size_t)MTOK * GH];   // 151MB fp16
__device__ __half g_qh[(size_t)MTOK * HH];
__device__ __half g_attnh[(size_t)MTOK * HH];
__device__ int    g_is64;

// ---------- helpers ----------
__device__ __forceinline__ uint32_t smem_u32(const void* p) {
    uint32_t a;
    asm("{ .reg .u64 t; cvta.to.shared.u64 t, %1; cvt.u32.u64 %0, t; }" : "=r"(a) : "l"(p));
    return a;
}
__device__ __forceinline__ void cp16(uint32_t saddr, const void* gptr) {
    asm volatile("cp.async.cg.shared.global [%0], [%1], 16;" :: "r"(saddr), "l"(gptr) : "memory");
}
__device__ __forceinline__ void cp16z(uint32_t saddr, const void* gptr, uint32_t srcsz) {
    asm volatile("cp.async.cg.shared.global [%0], [%1], 16, %2;"
                 :: "r"(saddr), "l"(gptr), "r"(srcsz) : "memory");
}
__device__ __forceinline__ void cp_commit() { asm volatile("cp.async.commit_group;" ::: "memory"); }
__device__ __forceinline__ void cp_wait2()  { asm volatile("cp.async.wait_group 2;" ::: "memory"); }

// A tile [128 m][32 k] halfs: row = 64B = 4 chunks of 16B (swizzled in 128B pairs)
__device__ __forceinline__ uint32_t swA(int r, int ch) {
    return (uint32_t)(r * 64 + ((ch ^ ((r >> 1) & 3)) << 4));
}
// B tile [32 k][128 n] halfs: row = 256B, 16 chunks of 16B, XOR-swizzled
__device__ __forceinline__ uint32_t swB(int k, int nch) {
    return (uint32_t)(k * 256 + ((nch ^ (k & 7)) << 4));
}
__device__ __forceinline__ void ldsm4(uint32_t* r, uint32_t addr) {
    asm volatile("ldmatrix.sync.aligned.m8n8.x4.shared.b16 {%0,%1,%2,%3}, [%4];"
                 : "=r"(r[0]), "=r"(r[1]), "=r"(r[2]), "=r"(r[3]) : "r"(addr));
}
__device__ __forceinline__ void ldsm4t(uint32_t& r0, uint32_t& r1, uint32_t& r2, uint32_t& r3,
                                       uint32_t addr) {
    asm volatile("ldmatrix.sync.aligned.m8n8.x4.trans.shared.b16 {%0,%1,%2,%3}, [%4];"
                 : "=r"(r0), "=r"(r1), "=r"(r2), "=r"(r3) : "r"(addr));
}
__device__ __forceinline__ void mma16816(float* d, const uint32_t* a, const uint32_t* b) {
    asm volatile(
        "mma.sync.aligned.m16n8k16.row.col.f32.f16.f16.f32 "
        "{%0,%1,%2,%3}, {%4,%5,%6,%7}, {%8,%9}, {%0,%1,%2,%3};"
        : "+f"(d[0]), "+f"(d[1]), "+f"(d[2]), "+f"(d[3])
        : "r"(a[0]), "r"(a[1]), "r"(a[2]), "r"(a[3]), "r"(b[0]), "r"(b[1]));
}

// ---------- detect int width of connections ----------
__global__ void detect_kernel(const int* __restrict__ conn) {
    if (threadIdx.x == 0 && blockIdx.x == 0) {
        int is64 = 1;
        #pragma unroll
        for (int i = 0; i < 64; i++) {
            if (conn[2 * i + 1] != 0) { is64 = 0; break; }
        }
        g_is64 = is64;
    }
}

// ---------- prep: convert all fp32 operands to fp16, 8 floats/thread ----------
#define H2  524288ull         // hidden float4-PAIRS
#define W2  10616832ull       // 9216*9216/8
#define S2  32768ull          // 512*512/8
__global__ void prep_kernel(const float4* __restrict__ hid, const float4* __restrict__ wk,
                            const float4* __restrict__ wv, const float4* __restrict__ wq,
                            const float4* __restrict__ wo,
                            uint4* __restrict__ hidh, uint4* __restrict__ wkh,
                            uint4* __restrict__ wvh, uint4* __restrict__ wqh,
                            uint4* __restrict__ woh) {
    size_t t = (size_t)blockIdx.x * blockDim.x + threadIdx.x;   // pair index
    const float4* src; uint4* dst; size_t p;
    if (t < H2)                       { src = hid; dst = hidh; p = t; }
    else if (t < H2 + W2)             { src = wk;  dst = wkh;  p = t - H2; }
    else if (t < H2 + 2*W2)           { src = wv;  dst = wvh;  p = t - H2 - W2; }
    else if (t < H2 + 2*W2 + S2)      { src = wq;  dst = wqh;  p = t - H2 - 2*W2; }
    else if (t < H2 + 2*W2 + 2*S2)    { src = wo;  dst = woh;  p = t - H2 - 2*W2 - S2; }
    else return;
    float4 v0 = src[2 * p];
    float4 v1 = src[2 * p + 1];
    union { __half2 h[4]; uint4 u; } pk;
    pk.h[0] = __floats2half2_rn(v0.x, v0.y);
    pk.h[1] = __floats2half2_rn(v0.z, v0.w);
    pk.h[2] = __floats2half2_rn(v1.x, v1.y);
    pk.h[3] = __floats2half2_rn(v1.z, v1.w);
    dst[p] = pk.u;
}

// ---------- fp16 tensor-core GEMM ----------
// C[M, Ntot] = A[M, Kdim] * B[Kdim, Ntot]   (B row-major K-major, ldmatrix.trans)
// GATHER: A row r of tile = hidden_h[b*SS + conn[token, g]], zeros if conn<0.
// HALF_OUT: write __half outputs; else fp32.
// Segments: n_id < n_split1 -> (B1,C1); < n_split2 -> (B2,C2);
// MERGEQ && n_id >= n_split2 -> (B3,C3) with NtotQ/nktQ and identity gather.
template<bool GATHER, bool HALF_OUT, bool MERGEQ>
__global__ __launch_bounds__(NTHR, 2)
void gemm_mma(const __half* __restrict__ Abase,
              const __half* __restrict__ B1, const __half* __restrict__ B2,
              const __half* __restrict__ B3,
              void* __restrict__ Cv1, void* __restrict__ Cv2, void* __restrict__ Cv3,
              const void* __restrict__ conn,
              int Kdim, int Ntot0, int n_tiles, int n_split1, int n_split2,
              int nkt0, int NtotQ, int nktQ) {
    extern __shared__ char smem[];
    uint32_t sbase = smem_u32(smem);
    int* sconn = (int*)(smem + SMEM_MAIN);
    int tid = threadIdx.x;
    int lane = tid & 31, w = tid >> 5;
    int wm = w >> 1, wn = w & 1;          // 2 (m) x 2 (n) warps, warp tile 64x64

    // grouped rasterization (n spans all segments -> A reuse in L2)
    int pid = blockIdx.x;
    int per_g = GROUPM * n_tiles;
    int g = pid / per_g;
    int rem = pid - g * per_g;
    int m_id = g * GROUPM + (rem % GROUPM);
    int n_id = rem / GROUPM;
    int tok0 = m_id * BKM;

    const __half* B;
    void* Cv;
    int n_loc;
    int Ntot = Ntot0, nkt = nkt0;
    bool isQ = false;
    if (n_id < n_split1)      { B = B1; Cv = Cv1; n_loc = n_id; }
    else if (n_id < n_split2) { B = B2; Cv = Cv2; n_loc = n_id - n_split1; }
    else                      { B = B3; Cv = Cv3; n_loc = n_id - n_split2;
                                Ntot = NtotQ; nkt = nktQ; isQ = true; }

    // preload + clip connection indices for this CTA's 128 tokens
    if (GATHER) {
        if (MERGEQ && isQ) {
            for (int i = tid; i < BKM * GG; i += NTHR)
                sconn[i] = (tok0 + i / GG) & (SS - 1);
        } else {
            int is64 = g_is64;
            for (int i = tid; i < BKM * GG; i += NTHR) {
                size_t idx = (size_t)(tok0 + i / GG) * GG + (i % GG);
                long long c = is64 ? ((const long long*)conn)[idx]
                                   : (long long)((const int*)conn)[idx];
                sconn[i] = c < 0 ? -1 : (c > SS - 1 ? SS - 1 : (int)c);
            }
        }
        __syncthreads();
    }

    // per-thread load coordinates (4 A chunks + 4 B chunks per stage)
    int rA[4], chA[4]; uint32_t soA[4];
    uint32_t soB[4]; const __half* gB[4];
    #pragma unroll
    for (int i = 0; i < 4; i++) {
        int cA = tid + i * NTHR;          // 0..511
        rA[i] = cA >> 2; chA[i] = cA & 3;
        soA[i] = swA(rA[i], chA[i]);
        int cB = tid + i * NTHR;
        int krB = cB >> 4; int nch = cB & 15;
        soB[i] = swB(krB, nch);
        gB[i] = B + (size_t)krB * Ntot + (size_t)n_loc * BKN + nch * 8;
    }
    const __half* hidb = GATHER ? Abase + ((size_t)(tok0 >> 12) << 12) * HH : nullptr;

    #define LOAD_TILE(s, kt)                                                       \
    do {                                                                           \
        uint32_t sA_ = sbase + (s) * SMEM_STAGE;                                   \
        uint32_t sB_ = sA_ + 8192;                                                 \
        int kb_ = (kt) * BKK;                                                      \
        if (GATHER) {                                                              \
            int gg_ = kb_ >> 9;                                                    \
            int off_ = kb_ & 511;                                                  \
            _Pragma("unroll")                                                      \
            for (int i = 0; i < 4; i++) {                                          \
                int idx_ = sconn[rA[i] * GG + gg_];                                \
                int idc_ = idx_ < 0 ? 0 : idx_;                                    \
                cp16z(sA_ + soA[i],                                                \
                      hidb + (size_t)idc_ * HH + off_ + chA[i] * 8,                \
                      idx_ < 0 ? 0u : 16u);                                        \
            }                                                                      \
        } else {                                                                   \
            _Pragma("unroll")                                                      \
            for (int i = 0; i < 4; i++)                                            \
                cp16(sA_ + soA[i],                                                 \
                     Abase + (size_t)(tok0 + rA[i]) * Kdim + kb_ + chA[i] * 8);    \
        }                                                                          \
        _Pragma("unroll")                                                          \
        for (int i = 0; i < 4; i++)                                                \
            cp16(sB_ + soB[i], gB[i] + (size_t)kb_ * Ntot);                        \
    } while (0)

    LOAD_TILE(0, 0); cp_commit();
    LOAD_TILE(1, 1); cp_commit();
    LOAD_TILE(2, 2); cp_commit();

    float acc[4][8][4] = {};

    int a_row = ((lane >> 3) & 1) * 8 + (lane & 7) + wm * 64;  // + mf*16
    int a_chb = lane >> 4;                                     // + kf*2
    int b_krb = ((lane >> 3) & 1) * 8 + (lane & 7);            // + kf*16
    int b_nchb = wn * 8 + (lane >> 4);                         // + np*2

    for (int kt = 0; kt < nkt; kt++) {
        int s = kt & (STAGES - 1);
        cp_wait2();
        __syncthreads();
        uint32_t sA = sbase + s * SMEM_STAGE;
        uint32_t sB = sA + 8192;

        #pragma unroll
        for (int kf = 0; kf < 2; kf++) {
            uint32_t af[4][4];
            uint32_t bf[8][2];
            #pragma unroll
            for (int mf = 0; mf < 4; mf++)
                ldsm4(af[mf], sA + swA(a_row + mf * 16, a_chb + kf * 2));
            #pragma unroll
            for (int np = 0; np < 4; np++) {
                uint32_t q0, q1, q2, q3;
                ldsm4t(q0, q1, q2, q3, sB + swB(b_krb + kf * 16, b_nchb + np * 2));
                bf[np * 2][0] = q0;     bf[np * 2][1] = q1;
                bf[np * 2 + 1][0] = q2; bf[np * 2 + 1][1] = q3;
            }
            #pragma unroll
            for (int mf = 0; mf < 4; mf++)
                #pragma unroll
                for (int nf = 0; nf < 8; nf++)
                    mma16816(acc[mf][nf], af[mf], bf[nf]);
        }

        if (kt + 3 < nkt) LOAD_TILE((kt + 3) & (STAGES - 1), kt + 3);
        cp_commit();
    }
    #undef LOAD_TILE

    // epilogue
    size_t cm = (size_t)tok0 + wm * 64;
    size_t cn = (size_t)n_loc * BKN + wn * 64;
    #pragma unroll
    for (int mf = 0; mf < 4; mf++) {
        #pragma unroll
        for (int nf = 0; nf < 8; nf++) {
            size_t row = cm + mf * 16 + (lane >> 2);
            size_t col = cn + nf * 8 + (lane & 3) * 2;
            if (HALF_OUT) {
                __half* C = (__half*)Cv;
                *(__half2*)&C[row * Ntot + col] = __floats2half2_rn(acc[mf][nf][0], acc[mf][nf][1]);
                *(__half2*)&C[(row + 8) * Ntot + col] = __floats2half2_rn(acc[mf][nf][2], acc[mf][nf][3]);
            } else {
                float* C = (float*)Cv;
                *(float2*)&C[row * Ntot + col] = make_float2(acc[mf][nf][0], acc[mf][nf][1]);
                *(float2*)&C[(row + 8) * Ntot + col] = make_float2(acc[mf][nf][2], acc[mf][nf][3]);
            }
        }
    }
}

// ---------- attention over G=18 connections (fp16 in, fp16 out) ----------
// 8B loads per lane: lane owns elements 4*lane..4*lane+3 of the 64-dim head.
__global__ __launch_bounds__(256)
void attn_kernel(const uint2* __restrict__ q, const uint2* __restrict__ key,
                 const uint2* __restrict__ val, uint2* __restrict__ outh) {
    int bs = blockIdx.x;
    int head = threadIdx.x >> 5;
    int lane = threadIdx.x & 31;
    int lane16 = lane & 15;               // element-quad within head (64/4=16)
    // two lanes (lane, lane^16) read the same data; harmless (broadcast in L1)

    union U2 { uint2 u; __half2 h[2]; };

    U2 qv; qv.u = q[((size_t)bs * HH + head * DD) / 4 + lane16];
    float2 q0 = __half22float2(qv.h[0]);
    float2 q1 = __half22float2(qv.h[1]);

    float sc[GG];
    const uint2* kb = key + ((size_t)bs * GH + head * DD) / 4 + lane16;
    #pragma unroll
    for (int j = 0; j < GG; j++) {
        U2 kv; kv.u = kb[(size_t)j * (HH / 4)];
        float2 k0 = __half22float2(kv.h[0]);
        float2 k1 = __half22float2(kv.h[1]);
        float s = q0.x * k0.x + q0.y * k0.y + q1.x * k1.x + q1.y * k1.y;
        // lanes 16..31 duplicate lanes 0..15; butterfly over 16 lanes suffices
        s += __shfl_xor_sync(0xFFFFFFFFu, s, 8);
        s += __shfl_xor_sync(0xFFFFFFFFu, s, 4);
        s += __shfl_xor_sync(0xFFFFFFFFu, s, 2);
        s += __shfl_xor_sync(0xFFFFFFFFu, s, 1);
        sc[j] = s * 0.125f;
    }
    float m = sc[0];
    #pragma unroll
    for (int j = 1; j < GG; j++) m = fmaxf(m, sc[j]);
    float sum = 0.f;
    #pragma unroll
    for (int j = 0; j < GG; j++) { sc[j] = __expf(sc[j] - m); sum += sc[j]; }
    float inv = 1.f / sum;

    float o0x = 0.f, o0y = 0.f, o1x = 0.f, o1y = 0.f;
    const uint2* vb = val + ((size_t)bs * GH + head * DD) / 4 + lane16;
    #pragma unroll
    for (int j = 0; j < GG; j++) {
        U2 vv; vv.u = vb[(size_t)j * (HH / 4)];
        float2 v0 = __half22float2(vv.h[0]);
        float2 v1 = __half22float2(vv.h[1]);
        o0x = fmaf(sc[j], v0.x, o0x); o0y = fmaf(sc[j], v0.y, o0y);
        o1x = fmaf(sc[j], v1.x, o1x); o1y = fmaf(sc[j], v1.y, o1y);
    }
    if (lane < 16) {
        U2 o;
        o.h[0] = __floats2half2_rn(o0x * inv, o0y * inv);
        o.h[1] = __floats2half2_rn(o1x * inv, o1y * inv);
        outh[((size_t)bs * HH + head * DD) / 4 + lane16] = o.u;
    }
}

// ---------- launch ----------
extern "C" void kernel_launch(void* const* d_in, const int* in_sizes, int n_in,
                              void* d_out, int out_size) {
    const float* hidden = (const float*)d_in[0];
    const void*  conn   = d_in[1];
    const float* Wq     = (const float*)d_in[2];
    const float* Wk     = (const float*)d_in[3];
    const float* Wv     = (const float*)d_in[4];
    const float* Wo     = (const float*)d_in[5];
    float* out = (float*)d_out;

    __half *pHid, *pWkh, *pWvh, *pWqh, *pWoh, *pKeyh, *pValh, *pQh, *pAttnh;
    cudaGetSymbolAddress((void**)&pHid,   g_hidh);
    cudaGetSymbolAddress((void**)&pWkh,   g_Wkh);
    cudaGetSymbolAddress((void**)&pWvh,   g_Wvh);
    cudaGetSymbolAddress((void**)&pWqh,   g_Wqh);
    cudaGetSymbolAddress((void**)&pWoh,   g_Woh);
    cudaGetSymbolAddress((void**)&pKeyh,  g_keyh);
    cudaGetSymbolAddress((void**)&pValh,  g_valh);
    cudaGetSymbolAddress((void**)&pQh,    g_qh);
    cudaGetSymbolAddress((void**)&pAttnh, g_attnh);

    cudaFuncSetAttribute((const void*)gemm_mma<true, true, true>,
                         cudaFuncAttributeMaxDynamicSharedMemorySize, SMEM_G);
    cudaFuncSetAttribute((const void*)gemm_mma<false, false, false>,
                         cudaFuncAttributeMaxDynamicSharedMemorySize, SMEM_G);

    // 1) int width detection
    detect_kernel<<<1, 32>>>((const int*)conn);

    // 2) fp16 conversion of all operands (16B stores)
    {
        size_t total = H2 + 2 * W2 + 2 * S2;
        prep_kernel<<<(unsigned)((total + 255) / 256), 256>>>(
            (const float4*)hidden, (const float4*)Wk, (const float4*)Wv,
            (const float4*)Wq, (const float4*)Wo,
            (uint4*)pHid, (uint4*)pWkh, (uint4*)pWvh, (uint4*)pWqh, (uint4*)pWoh);
    }

    // 3) key+value+query in ONE launch: n tiles span Wk|Wv|Wq
    {
        int n_tiles = KV_TILES + Q_TILES;          // 148
        int grid = (MTOK / BKM) * n_tiles;         // 9472
        gemm_mma<true, true, true><<<grid, NTHR, SMEM_G>>>(
            pHid, pWkh, pWvh, pWqh, pKeyh, pValh, pQh, conn,
            GH, GH, n_tiles, GH / BKN, KV_TILES, GH / BKK, HH, HH / BKK);
    }

    // 4) attention (fp16 in/out, 8B loads)
    attn_kernel<<<MTOK, 256>>>((const uint2*)pQh, (const uint2*)pKeyh,
                               (const uint2*)pValh, (uint2*)pAttnh);

    // 5) out = attn @ Wo -> fp32
    gemm_mma<false, false, false><<<(MTOK / BKM) * (HH / BKN), NTHR, SMEM_G>>>(
        pAttnh, pWoh, pWoh, pWoh, out, out, out, nullptr,
        HH, HH, HH / BKN, HH / BKN, HH / BKN, HH / BKK, HH, HH / BKK);
}

// round 15
// speedup vs baseline: 1.0013x; 1.0012x over previous
#include <cuda_runtime.h>
#include <cuda_fp16.h>
#include <cstdint>

// Problem constants
#define BB 2
#define SS 4096
#define HH 512
#define GG 18
#define NHEAD 8
#define DD 64
#define GH (GG*HH)        // 9216
#define MTOK (BB*SS)      // 8192

// mma GEMM config: CTA 128x128, 4 warps (2m x 2n), warp tile 64x64, BKK=32
#define BKM 128
#define BKN 128
#define BKK 32
#define GROUPM 32
#define STAGES 4
#define NTHR 128
#define SMEM_STAGE 16384                 // A 8KB + B 8KB
#define SMEM_MAIN (STAGES*SMEM_STAGE)    // 65536
#define SMEM_CONN (128*GG*4)             // 9216
#define SMEM_G (SMEM_MAIN + SMEM_CONN)   // 74752

#define KV_TILES (2*(GH/BKN))            // 144
#define Q_TILES  (HH/BKN)                // 4

// ---------- static device scratch ----------
__device__ __half g_hidh[(size_t)MTOK * HH];   // hidden fp16 (16MB)
__device__ __half g_Wkh[(size_t)GH * GH];      // Wk fp16 [K,N] (170MB)
__device__ __half g_Wvh[(size_t)GH * GH];
__device__ __half g_Wqh[(size_t)HH * HH];
__device__ __half g_Woh[(size_t)HH * HH];
__device__ __half g_keyh[(size_t)MTOK * GH];   // 151MB fp16
__device__ __half g_valh[(size_t)MTOK * GH];   // 151MB fp16
__device__ __half g_qh[(size_t)MTOK * HH];
__device__ __half g_attnh[(size_t)MTOK * HH];
__device__ int    g_is64;

// ---------- helpers ----------
__device__ __forceinline__ uint32_t smem_u32(const void* p) {
    uint32_t a;
    asm("{ .reg .u64 t; cvta.to.shared.u64 t, %1; cvt.u32.u64 %0, t; }" : "=r"(a) : "l"(p));
    return a;
}
__device__ __forceinline__ void cp16(uint32_t saddr, const void* gptr) {
    asm volatile("cp.async.cg.shared.global [%0], [%1], 16;" :: "r"(saddr), "l"(gptr) : "memory");
}
__device__ __forceinline__ void cp16z(uint32_t saddr, const void* gptr, uint32_t srcsz) {
    asm volatile("cp.async.cg.shared.global [%0], [%1], 16, %2;"
                 :: "r"(saddr), "l"(gptr), "r"(srcsz) : "memory");
}
__device__ __forceinline__ void cp_commit() { asm volatile("cp.async.commit_group;" ::: "memory"); }
__device__ __forceinline__ void cp_wait2()  { asm volatile("cp.async.wait_group 2;" ::: "memory"); }

// A tile [128 m][32 k] halfs: row = 64B = 4 chunks of 16B (swizzled in 128B pairs)
__device__ __forceinline__ uint32_t swA(int r, int ch) {
    return (uint32_t)(r * 64 + ((ch ^ ((r >> 1) & 3)) << 4));
}
// B tile [32 k][128 n] halfs: row = 256B, 16 chunks of 16B, XOR-swizzled
__device__ __forceinline__ uint32_t swB(int k, int nch) {
    return (uint32_t)(k * 256 + ((nch ^ (k & 7)) << 4));
}
__device__ __forceinline__ void ldsm4(uint32_t* r, uint32_t addr) {
    asm volatile("ldmatrix.sync.aligned.m8n8.x4.shared.b16 {%0,%1,%2,%3}, [%4];"
                 : "=r"(r[0]), "=r"(r[1]), "=r"(r[2]), "=r"(r[3]) : "r"(addr));
}
__device__ __forceinline__ void ldsm4t(uint32_t& r0, uint32_t& r1, uint32_t& r2, uint32_t& r3,
                                       uint32_t addr) {
    asm volatile("ldmatrix.sync.aligned.m8n8.x4.trans.shared.b16 {%0,%1,%2,%3}, [%4];"
                 : "=r"(r0), "=r"(r1), "=r"(r2), "=r"(r3) : "r"(addr));
}
__device__ __forceinline__ void mma16816(float* d, const uint32_t* a, const uint32_t* b) {
    asm volatile(
        "mma.sync.aligned.m16n8k16.row.col.f32.f16.f16.f32 "
        "{%0,%1,%2,%3}, {%4,%5,%6,%7}, {%8,%9}, {%0,%1,%2,%3};"
        : "+f"(d[0]), "+f"(d[1]), "+f"(d[2]), "+f"(d[3])
        : "r"(a[0]), "r"(a[1]), "r"(a[2]), "r"(a[3]), "r"(b[0]), "r"(b[1]));
}

// ---------- detect int width of connections ----------
__global__ void detect_kernel(const int* __restrict__ conn) {
    if (threadIdx.x == 0 && blockIdx.x == 0) {
        int is64 = 1;
        #pragma unroll
        for (int i = 0; i < 64; i++) {
            if (conn[2 * i + 1] != 0) { is64 = 0; break; }
        }
        g_is64 = is64;
    }
}

// ---------- prep: convert all fp32 operands to fp16, 8 floats/thread ----------
#define H2  524288ull         // hidden float4-PAIRS
#define W2  10616832ull       // 9216*9216/8
#define S2  32768ull          // 512*512/8
__global__ void prep_kernel(const float4* __restrict__ hid, const float4* __restrict__ wk,
                            const float4* __restrict__ wv, const float4* __restrict__ wq,
                            const float4* __restrict__ wo,
                            uint4* __restrict__ hidh, uint4* __restrict__ wkh,
                            uint4* __restrict__ wvh, uint4* __restrict__ wqh,
                            uint4* __restrict__ woh) {
    size_t t = (size_t)blockIdx.x * blockDim.x + threadIdx.x;   // pair index
    const float4* src; uint4* dst; size_t p;
    if (t < H2)                       { src = hid; dst = hidh; p = t; }
    else if (t < H2 + W2)             { src = wk;  dst = wkh;  p = t - H2; }
    else if (t < H2 + 2*W2)           { src = wv;  dst = wvh;  p = t - H2 - W2; }
    else if (t < H2 + 2*W2 + S2)      { src = wq;  dst = wqh;  p = t - H2 - 2*W2; }
    else if (t < H2 + 2*W2 + 2*S2)    { src = wo;  dst = woh;  p = t - H2 - 2*W2 - S2; }
    else return;
    float4 v0 = src[2 * p];
    float4 v1 = src[2 * p + 1];
    union { __half2 h[4]; uint4 u; } pk;
    pk.h[0] = __floats2half2_rn(v0.x, v0.y);
    pk.h[1] = __floats2half2_rn(v0.z, v0.w);
    pk.h[2] = __floats2half2_rn(v1.x, v1.y);
    pk.h[3] = __floats2half2_rn(v1.z, v1.w);
    dst[p] = pk.u;
}

// ---------- fp16 tensor-core GEMM ----------
// C[M, Ntot] = A[M, Kdim] * B[Kdim, Ntot]   (B row-major K-major, ldmatrix.trans)
// GATHER: A row r of tile = hidden_h[b*SS + conn[token, g]], zeros if conn<0.
// HALF_OUT: write __half outputs; else fp32.
// Segments: n_id < n_split1 -> (B1,C1); < n_split2 -> (B2,C2);
// MERGEQ && n_id >= n_split2 -> (B3,C3) with NtotQ/nktQ and identity gather.
template<bool GATHER, bool HALF_OUT, bool MERGEQ>
__global__ __launch_bounds__(NTHR, 2)
void gemm_mma(const __half* __restrict__ Abase,
              const __half* __restrict__ B1, const __half* __restrict__ B2,
              const __half* __restrict__ B3,
              void* __restrict__ Cv1, void* __restrict__ Cv2, void* __restrict__ Cv3,
              const void* __restrict__ conn,
              int Kdim, int Ntot0, int n_tiles, int n_split1, int n_split2,
              int nkt0, int NtotQ, int nktQ) {
    extern __shared__ char smem[];
    uint32_t sbase = smem_u32(smem);
    int* sconn = (int*)(smem + SMEM_MAIN);
    int tid = threadIdx.x;
    int lane = tid & 31, w = tid >> 5;
    int wm = w >> 1, wn = w & 1;          // 2 (m) x 2 (n) warps, warp tile 64x64

    // grouped rasterization (n spans all segments -> A reuse in L2)
    int pid = blockIdx.x;
    int per_g = GROUPM * n_tiles;
    int g = pid / per_g;
    int rem = pid - g * per_g;
    int m_id = g * GROUPM + (rem % GROUPM);
    int n_id = rem / GROUPM;
    int tok0 = m_id * BKM;

    const __half* B;
    void* Cv;
    int n_loc;
    int Ntot = Ntot0, nkt = nkt0;
    bool isQ = false;
    if (n_id < n_split1)      { B = B1; Cv = Cv1; n_loc = n_id; }
    else if (n_id < n_split2) { B = B2; Cv = Cv2; n_loc = n_id - n_split1; }
    else                      { B = B3; Cv = Cv3; n_loc = n_id - n_split2;
                                Ntot = NtotQ; nkt = nktQ; isQ = true; }

    // preload + clip connection indices for this CTA's 128 tokens
    if (GATHER) {
        if (MERGEQ && isQ) {
            for (int i = tid; i < BKM * GG; i += NTHR)
                sconn[i] = (tok0 + i / GG) & (SS - 1);
        } else {
            int is64 = g_is64;
            for (int i = tid; i < BKM * GG; i += NTHR) {
                size_t idx = (size_t)(tok0 + i / GG) * GG + (i % GG);
                long long c = is64 ? ((const long long*)conn)[idx]
                                   : (long long)((const int*)conn)[idx];
                sconn[i] = c < 0 ? -1 : (c > SS - 1 ? SS - 1 : (int)c);
            }
        }
        __syncthreads();
    }

    // per-thread load coordinates (4 A chunks + 4 B chunks per stage)
    int rA[4], chA[4]; uint32_t soA[4];
    uint32_t soB[4]; const __half* gB[4];
    #pragma unroll
    for (int i = 0; i < 4; i++) {
        int cA = tid + i * NTHR;          // 0..511
        rA[i] = cA >> 2; chA[i] = cA & 3;
        soA[i] = swA(rA[i], chA[i]);
        int cB = tid + i * NTHR;
        int krB = cB >> 4; int nch = cB & 15;
        soB[i] = swB(krB, nch);
        gB[i] = B + (size_t)krB * Ntot + (size_t)n_loc * BKN + nch * 8;
    }
    const __half* hidb = GATHER ? Abase + ((size_t)(tok0 >> 12) << 12) * HH : nullptr;

    #define LOAD_TILE(s, kt)                                                       \
    do {                                                                           \
        uint32_t sA_ = sbase + (s) * SMEM_STAGE;                                   \
        uint32_t sB_ = sA_ + 8192;                                                 \
        int kb_ = (kt) * BKK;                                                      \
        if (GATHER) {                                                              \
            int gg_ = kb_ >> 9;                                                    \
            int off_ = kb_ & 511;                                                  \
            _Pragma("unroll")                                                      \
            for (int i = 0; i < 4; i++) {                                          \
                int idx_ = sconn[rA[i] * GG + gg_];                                \
                int idc_ = idx_ < 0 ? 0 : idx_;                                    \
                cp16z(sA_ + soA[i],                                                \
                      hidb + (size_t)idc_ * HH + off_ + chA[i] * 8,                \
                      idx_ < 0 ? 0u : 16u);                                        \
            }                                                                      \
        } else {                                                                   \
            _Pragma("unroll")                                                      \
            for (int i = 0; i < 4; i++)                                            \
                cp16(sA_ + soA[i],                                                 \
                     Abase + (size_t)(tok0 + rA[i]) * Kdim + kb_ + chA[i] * 8);    \
        }                                                                          \
        _Pragma("unroll")                                                          \
        for (int i = 0; i < 4; i++)                                                \
            cp16(sB_ + soB[i], gB[i] + (size_t)kb_ * Ntot);                        \
    } while (0)

    LOAD_TILE(0, 0); cp_commit();
    LOAD_TILE(1, 1); cp_commit();
    LOAD_TILE(2, 2); cp_commit();

    float acc[4][8][4] = {};

    int a_row = ((lane >> 3) & 1) * 8 + (lane & 7) + wm * 64;  // + mf*16
    int a_chb = lane >> 4;                                     // + kf*2
    int b_krb = ((lane >> 3) & 1) * 8 + (lane & 7);            // + kf*16
    int b_nchb = wn * 8 + (lane >> 4);                         // + np*2

    for (int kt = 0; kt < nkt; kt++) {
        int s = kt & (STAGES - 1);
        cp_wait2();
        __syncthreads();
        uint32_t sA = sbase + s * SMEM_STAGE;
        uint32_t sB = sA + 8192;

        #pragma unroll
        for (int kf = 0; kf < 2; kf++) {
            uint32_t af[4][4];
            uint32_t bf[8][2];
            #pragma unroll
            for (int mf = 0; mf < 4; mf++)
                ldsm4(af[mf], sA + swA(a_row + mf * 16, a_chb + kf * 2));
            #pragma unroll
            for (int np = 0; np < 4; np++) {
                uint32_t q0, q1, q2, q3;
                ldsm4t(q0, q1, q2, q3, sB + swB(b_krb + kf * 16, b_nchb + np * 2));
                bf[np * 2][0] = q0;     bf[np * 2][1] = q1;
                bf[np * 2 + 1][0] = q2; bf[np * 2 + 1][1] = q3;
            }
            #pragma unroll
            for (int mf = 0; mf < 4; mf++)
                #pragma unroll
                for (int nf = 0; nf < 8; nf++)
                    mma16816(acc[mf][nf], af[mf], bf[nf]);
        }

        if (kt + 3 < nkt) LOAD_TILE((kt + 3) & (STAGES - 1), kt + 3);
        cp_commit();
    }
    #undef LOAD_TILE

    // epilogue
    size_t cm = (size_t)tok0 + wm * 64;
    size_t cn = (size_t)n_loc * BKN + wn * 64;
    #pragma unroll
    for (int mf = 0; mf < 4; mf++) {
        #pragma unroll
        for (int nf = 0; nf < 8; nf++) {
            size_t row = cm + mf * 16 + (lane >> 2);
            size_t col = cn + nf * 8 + (lane & 3) * 2;
            if (HALF_OUT) {
                __half* C = (__half*)Cv;
                *(__half2*)&C[row * Ntot + col] = __floats2half2_rn(acc[mf][nf][0], acc[mf][nf][1]);
                *(__half2*)&C[(row + 8) * Ntot + col] = __floats2half2_rn(acc[mf][nf][2], acc[mf][nf][3]);
            } else {
                float* C = (float*)Cv;
                *(float2*)&C[row * Ntot + col] = make_float2(acc[mf][nf][0], acc[mf][nf][1]);
                *(float2*)&C[(row + 8) * Ntot + col] = make_float2(acc[mf][nf][2], acc[mf][nf][3]);
            }
        }
    }
}

// ---------- attention over G=18 connections (fp16 in, fp16 out) ----------
__global__ __launch_bounds__(256)
void attn_kernel(const __half2* __restrict__ q, const __half2* __restrict__ key,
                 const __half2* __restrict__ val, __half2* __restrict__ outh) {
    int bs = blockIdx.x;
    int head = threadIdx.x >> 5;
    int lane = threadIdx.x & 31;

    float2 qv = __half22float2(q[((size_t)bs * HH + head * DD) / 2 + lane]);

    float sc[GG];
    const __half2* kb = key + ((size_t)bs * GH + head * DD) / 2 + lane;
    #pragma unroll
    for (int j = 0; j < GG; j++) {
        float2 kv = __half22float2(kb[(size_t)j * (HH / 2)]);
        float s = qv.x * kv.x + qv.y * kv.y;
        s += __shfl_xor_sync(0xFFFFFFFFu, s, 16);
        s += __shfl_xor_sync(0xFFFFFFFFu, s, 8);
        s += __shfl_xor_sync(0xFFFFFFFFu, s, 4);
        s += __shfl_xor_sync(0xFFFFFFFFu, s, 2);
        s += __shfl_xor_sync(0xFFFFFFFFu, s, 1);
        sc[j] = s * 0.125f;
    }
    float m = sc[0];
    #pragma unroll
    for (int j = 1; j < GG; j++) m = fmaxf(m, sc[j]);
    float sum = 0.f;
    #pragma unroll
    for (int j = 0; j < GG; j++) { sc[j] = __expf(sc[j] - m); sum += sc[j]; }
    float inv = 1.f / sum;

    float ox = 0.f, oy = 0.f;
    const __half2* vb = val + ((size_t)bs * GH + head * DD) / 2 + lane;
    #pragma unroll
    for (int j = 0; j < GG; j++) {
        float2 vv = __half22float2(vb[(size_t)j * (HH / 2)]);
        ox = fmaf(sc[j], vv.x, ox);
        oy = fmaf(sc[j], vv.y, oy);
    }
    outh[((size_t)bs * HH + head * DD) / 2 + lane] = __floats2half2_rn(ox * inv, oy * inv);
}

// ---------- launch ----------
extern "C" void kernel_launch(void* const* d_in, const int* in_sizes, int n_in,
                              void* d_out, int out_size) {
    const float* hidden = (const float*)d_in[0];
    const void*  conn   = d_in[1];
    const float* Wq     = (const float*)d_in[2];
    const float* Wk     = (const float*)d_in[3];
    const float* Wv     = (const float*)d_in[4];
    const float* Wo     = (const float*)d_in[5];
    float* out = (float*)d_out;

    __half *pHid, *pWkh, *pWvh, *pWqh, *pWoh, *pKeyh, *pValh, *pQh, *pAttnh;
    cudaGetSymbolAddress((void**)&pHid,   g_hidh);
    cudaGetSymbolAddress((void**)&pWkh,   g_Wkh);
    cudaGetSymbolAddress((void**)&pWvh,   g_Wvh);
    cudaGetSymbolAddress((void**)&pWqh,   g_Wqh);
    cudaGetSymbolAddress((void**)&pWoh,   g_Woh);
    cudaGetSymbolAddress((void**)&pKeyh,  g_keyh);
    cudaGetSymbolAddress((void**)&pValh,  g_valh);
    cudaGetSymbolAddress((void**)&pQh,    g_qh);
    cudaGetSymbolAddress((void**)&pAttnh, g_attnh);

    cudaFuncSetAttribute((const void*)gemm_mma<true, true, true>,
                         cudaFuncAttributeMaxDynamicSharedMemorySize, SMEM_G);
    cudaFuncSetAttribute((const void*)gemm_mma<false, false, false>,
                         cudaFuncAttributeMaxDynamicSharedMemorySize, SMEM_G);

    // 1) int width detection
    detect_kernel<<<1, 32>>>((const int*)conn);

    // 2) fp16 conversion of all operands (16B stores)
    {
        size_t total = H2 + 2 * W2 + 2 * S2;
        prep_kernel<<<(unsigned)((total + 255) / 256), 256>>>(
            (const float4*)hidden, (const float4*)Wk, (const float4*)Wv,
            (const float4*)Wq, (const float4*)Wo,
            (uint4*)pHid, (uint4*)pWkh, (uint4*)pWvh, (uint4*)pWqh, (uint4*)pWoh);
    }

    // 3) key+value+query in ONE launch: n tiles span Wk|Wv|Wq
    {
        int n_tiles = KV_TILES + Q_TILES;          // 148
        int grid = (MTOK / BKM) * n_tiles;         // 9472
        gemm_mma<true, true, true><<<grid, NTHR, SMEM_G>>>(
            pHid, pWkh, pWvh, pWqh, pKeyh, pValh, pQh, conn,
            GH, GH, n_tiles, GH / BKN, KV_TILES, GH / BKK, HH, HH / BKK);
    }

    // 4) attention (fp16 in/out)
    attn_kernel<<<MTOK, 256>>>((const __half2*)pQh, (const __half2*)pKeyh,
                               (const __half2*)pValh, (__half2*)pAttnh);

    // 5) out = attn @ Wo -> fp32
    gemm_mma<false, false, false><<<(MTOK / BKM) * (HH / BKN), NTHR, SMEM_G>>>(
        pAttnh, pWoh, pWoh, pWoh, out, out, out, nullptr,
        HH, HH, HH / BKN, HH / BKN, HH / BKN, HH / BKK, HH, HH / BKK);
}

// round 16
// speedup vs baseline: 1.0063x; 1.0050x over previous
#include <cuda_runtime.h>
#include <cuda_fp16.h>
#include <cstdint>

// Problem constants
#define BB 2
#define SS 4096
#define HH 512
#define GG 18
#define NHEAD 8
#define DD 64
#define GH (GG*HH)        // 9216
#define MTOK (BB*SS)      // 8192

// mma GEMM config: CTA 128x128, 4 warps (2m x 2n), warp tile 64x64, BKK=32
#define BKM 128
#define BKN 128
#define BKK 32
#define GROUPM 32
#define STAGES 5
#define NTHR 128
#define SMEM_STAGE 16384                 // A 8KB + B 8KB
#define SMEM_MAIN (STAGES*SMEM_STAGE)    // 81920
#define SMEM_CONN (128*GG*4)             // 9216
#define SMEM_G (SMEM_MAIN + SMEM_CONN)   // 91136

#define KV_TILES (2*(GH/BKN))            // 144
#define Q_TILES  (HH/BKN)                // 4

// ---------- static device scratch ----------
__device__ __half g_hidh[(size_t)MTOK * HH];   // hidden fp16 (16MB)
__device__ __half g_Wkh[(size_t)GH * GH];      // Wk fp16 [K,N] (170MB)
__device__ __half g_Wvh[(size_t)GH * GH];
__device__ __half g_Wqh[(size_t)HH * HH];
__device__ __half g_Woh[(size_t)HH * HH];
__device__ __half g_keyh[(size_t)MTOK * GH];   // 151MB fp16
__device__ __half g_valh[(size_t)MTOK * GH];   // 151MB fp16
__device__ __half g_qh[(size_t)MTOK * HH];
__device__ __half g_attnh[(size_t)MTOK * HH];
__device__ int    g_is64;

// ---------- helpers ----------
__device__ __forceinline__ uint32_t smem_u32(const void* p) {
    uint32_t a;
    asm("{ .reg .u64 t; cvta.to.shared.u64 t, %1; cvt.u32.u64 %0, t; }" : "=r"(a) : "l"(p));
    return a;
}
__device__ __forceinline__ void cp16(uint32_t saddr, const void* gptr) {
    asm volatile("cp.async.cg.shared.global [%0], [%1], 16;" :: "r"(saddr), "l"(gptr) : "memory");
}
__device__ __forceinline__ void cp16z(uint32_t saddr, const void* gptr, uint32_t srcsz) {
    asm volatile("cp.async.cg.shared.global [%0], [%1], 16, %2;"
                 :: "r"(saddr), "l"(gptr), "r"(srcsz) : "memory");
}
__device__ __forceinline__ void cp_commit() { asm volatile("cp.async.commit_group;" ::: "memory"); }
__device__ __forceinline__ void cp_wait3()  { asm volatile("cp.async.wait_group 3;" ::: "memory"); }

// A tile [128 m][32 k] halfs: row = 64B = 4 chunks of 16B (swizzled in 128B pairs)
__device__ __forceinline__ uint32_t swA(int r, int ch) {
    return (uint32_t)(r * 64 + ((ch ^ ((r >> 1) & 3)) << 4));
}
// B tile [32 k][128 n] halfs: row = 256B, 16 chunks of 16B, XOR-swizzled
__device__ __forceinline__ uint32_t swB(int k, int nch) {
    return (uint32_t)(k * 256 + ((nch ^ (k & 7)) << 4));
}
__device__ __forceinline__ void ldsm4(uint32_t* r, uint32_t addr) {
    asm volatile("ldmatrix.sync.aligned.m8n8.x4.shared.b16 {%0,%1,%2,%3}, [%4];"
                 : "=r"(r[0]), "=r"(r[1]), "=r"(r[2]), "=r"(r[3]) : "r"(addr));
}
__device__ __forceinline__ void ldsm4t(uint32_t& r0, uint32_t& r1, uint32_t& r2, uint32_t& r3,
                                       uint32_t addr) {
    asm volatile("ldmatrix.sync.aligned.m8n8.x4.trans.shared.b16 {%0,%1,%2,%3}, [%4];"
                 : "=r"(r0), "=r"(r1), "=r"(r2), "=r"(r3) : "r"(addr));
}
__device__ __forceinline__ void mma16816(float* d, const uint32_t* a, const uint32_t* b) {
    asm volatile(
        "mma.sync.aligned.m16n8k16.row.col.f32.f16.f16.f32 "
        "{%0,%1,%2,%3}, {%4,%5,%6,%7}, {%8,%9}, {%0,%1,%2,%3};"
        : "+f"(d[0]), "+f"(d[1]), "+f"(d[2]), "+f"(d[3])
        : "r"(a[0]), "r"(a[1]), "r"(a[2]), "r"(a[3]), "r"(b[0]), "r"(b[1]));
}

// ---------- detect int width of connections ----------
__global__ void detect_kernel(const int* __restrict__ conn) {
    if (threadIdx.x == 0 && blockIdx.x == 0) {
        int is64 = 1;
        #pragma unroll
        for (int i = 0; i < 64; i++) {
            if (conn[2 * i + 1] != 0) { is64 = 0; break; }
        }
        g_is64 = is64;
    }
}

// ---------- prep: convert all fp32 operands to fp16, 8 floats/thread ----------
#define H2  524288ull         // hidden float4-PAIRS
#define W2  10616832ull       // 9216*9216/8
#define S2  32768ull          // 512*512/8
__global__ void prep_kernel(const float4* __restrict__ hid, const float4* __restrict__ wk,
                            const float4* __restrict__ wv, const float4* __restrict__ wq,
                            const float4* __restrict__ wo,
                            uint4* __restrict__ hidh, uint4* __restrict__ wkh,
                            uint4* __restrict__ wvh, uint4* __restrict__ wqh,
                            uint4* __restrict__ woh) {
    size_t t = (size_t)blockIdx.x * blockDim.x + threadIdx.x;   // pair index
    const float4* src; uint4* dst; size_t p;
    if (t < H2)                       { src = hid; dst = hidh; p = t; }
    else if (t < H2 + W2)             { src = wk;  dst = wkh;  p = t - H2; }
    else if (t < H2 + 2*W2)           { src = wv;  dst = wvh;  p = t - H2 - W2; }
    else if (t < H2 + 2*W2 + S2)      { src = wq;  dst = wqh;  p = t - H2 - 2*W2; }
    else if (t < H2 + 2*W2 + 2*S2)    { src = wo;  dst = woh;  p = t - H2 - 2*W2 - S2; }
    else return;
    float4 v0 = src[2 * p];
    float4 v1 = src[2 * p + 1];
    union { __half2 h[4]; uint4 u; } pk;
    pk.h[0] = __floats2half2_rn(v0.x, v0.y);
    pk.h[1] = __floats2half2_rn(v0.z, v0.w);
    pk.h[2] = __floats2half2_rn(v1.x, v1.y);
    pk.h[3] = __floats2half2_rn(v1.z, v1.w);
    dst[p] = pk.u;
}

// ---------- fp16 tensor-core GEMM ----------
// C[M, Ntot] = A[M, Kdim] * B[Kdim, Ntot]   (B row-major K-major, ldmatrix.trans)
// GATHER: A row r of tile = hidden_h[b*SS + conn[token, g]], zeros if conn<0.
// HALF_OUT: write __half outputs; else fp32.
// Segments: n_id < n_split1 -> (B1,C1); < n_split2 -> (B2,C2);
// MERGEQ && n_id >= n_split2 -> (B3,C3) with NtotQ/nktQ and identity gather.
template<bool GATHER, bool HALF_OUT, bool MERGEQ>
__global__ __launch_bounds__(NTHR, 2)
void gemm_mma(const __half* __restrict__ Abase,
              const __half* __restrict__ B1, const __half* __restrict__ B2,
              const __half* __restrict__ B3,
              void* __restrict__ Cv1, void* __restrict__ Cv2, void* __restrict__ Cv3,
              const void* __restrict__ conn,
              int Kdim, int Ntot0, int n_tiles, int n_split1, int n_split2,
              int nkt0, int NtotQ, int nktQ) {
    extern __shared__ char smem[];
    uint32_t sbase = smem_u32(smem);
    int* sconn = (int*)(smem + SMEM_MAIN);
    int tid = threadIdx.x;
    int lane = tid & 31, w = tid >> 5;
    int wm = w >> 1, wn = w & 1;          // 2 (m) x 2 (n) warps, warp tile 64x64

    // grouped rasterization (n spans all segments -> A reuse in L2)
    int pid = blockIdx.x;
    int per_g = GROUPM * n_tiles;
    int g = pid / per_g;
    int rem = pid - g * per_g;
    int m_id = g * GROUPM + (rem % GROUPM);
    int n_id = rem / GROUPM;
    int tok0 = m_id * BKM;

    const __half* B;
    void* Cv;
    int n_loc;
    int Ntot = Ntot0, nkt = nkt0;
    bool isQ = false;
    if (n_id < n_split1)      { B = B1; Cv = Cv1; n_loc = n_id; }
    else if (n_id < n_split2) { B = B2; Cv = Cv2; n_loc = n_id - n_split1; }
    else                      { B = B3; Cv = Cv3; n_loc = n_id - n_split2;
                                Ntot = NtotQ; nkt = nktQ; isQ = true; }

    // preload + clip connection indices for this CTA's 128 tokens
    if (GATHER) {
        if (MERGEQ && isQ) {
            for (int i = tid; i < BKM * GG; i += NTHR)
                sconn[i] = (tok0 + i / GG) & (SS - 1);
        } else {
            int is64 = g_is64;
            for (int i = tid; i < BKM * GG; i += NTHR) {
                size_t idx = (size_t)(tok0 + i / GG) * GG + (i % GG);
                long long c = is64 ? ((const long long*)conn)[idx]
                                   : (long long)((const int*)conn)[idx];
                sconn[i] = c < 0 ? -1 : (c > SS - 1 ? SS - 1 : (int)c);
            }
        }
        __syncthreads();
    }

    // per-thread load coordinates (4 A chunks + 4 B chunks per stage)
    int rA[4], chA[4]; uint32_t soA[4];
    uint32_t soB[4]; const __half* gB[4];
    #pragma unroll
    for (int i = 0; i < 4; i++) {
        int cA = tid + i * NTHR;          // 0..511
        rA[i] = cA >> 2; chA[i] = cA & 3;
        soA[i] = swA(rA[i], chA[i]);
        int cB = tid + i * NTHR;
        int krB = cB >> 4; int nch = cB & 15;
        soB[i] = swB(krB, nch);
        gB[i] = B + (size_t)krB * Ntot + (size_t)n_loc * BKN + nch * 8;
    }
    const __half* hidb = GATHER ? Abase + ((size_t)(tok0 >> 12) << 12) * HH : nullptr;

    #define LOAD_TILE(s, kt)                                                       \
    do {                                                                           \
        uint32_t sA_ = sbase + (s) * SMEM_STAGE;                                   \
        uint32_t sB_ = sA_ + 8192;                                                 \
        int kb_ = (kt) * BKK;                                                      \
        if (GATHER) {                                                              \
            int gg_ = kb_ >> 9;                                                    \
            int off_ = kb_ & 511;                                                  \
            _Pragma("unroll")                                                      \
            for (int i = 0; i < 4; i++) {                                          \
                int idx_ = sconn[rA[i] * GG + gg_];                                \
                int idc_ = idx_ < 0 ? 0 : idx_;                                    \
                cp16z(sA_ + soA[i],                                                \
                      hidb + (size_t)idc_ * HH + off_ + chA[i] * 8,                \
                      idx_ < 0 ? 0u : 16u);                                        \
            }                                                                      \
        } else {                                                                   \
            _Pragma("unroll")                                                      \
            for (int i = 0; i < 4; i++)                                            \
                cp16(sA_ + soA[i],                                                 \
                     Abase + (size_t)(tok0 + rA[i]) * Kdim + kb_ + chA[i] * 8);    \
        }                                                                          \
        _Pragma("unroll")                                                          \
        for (int i = 0; i < 4; i++)                                                \
            cp16(sB_ + soB[i], gB[i] + (size_t)kb_ * Ntot);                        \
    } while (0)

    LOAD_TILE(0, 0); cp_commit();
    LOAD_TILE(1, 1); cp_commit();
    LOAD_TILE(2, 2); cp_commit();
    LOAD_TILE(3, 3); cp_commit();

    float acc[4][8][4] = {};

    int a_row = ((lane >> 3) & 1) * 8 + (lane & 7) + wm * 64;  // + mf*16
    int a_chb = lane >> 4;                                     // + kf*2
    int b_krb = ((lane >> 3) & 1) * 8 + (lane & 7);            // + kf*16
    int b_nchb = wn * 8 + (lane >> 4);                         // + np*2

    int s = 0, ls = 4;                    // consume / load stage counters (mod 5)
    for (int kt = 0; kt < nkt; kt++) {
        cp_wait3();
        __syncthreads();
        uint32_t sA = sbase + s * SMEM_STAGE;
        uint32_t sB = sA + 8192;

        #pragma unroll
        for (int kf = 0; kf < 2; kf++) {
            uint32_t af[4][4];
            uint32_t bf[8][2];
            #pragma unroll
            for (int mf = 0; mf < 4; mf++)
                ldsm4(af[mf], sA + swA(a_row + mf * 16, a_chb + kf * 2));
            #pragma unroll
            for (int np = 0; np < 4; np++) {
                uint32_t q0, q1, q2, q3;
                ldsm4t(q0, q1, q2, q3, sB + swB(b_krb + kf * 16, b_nchb + np * 2));
                bf[np * 2][0] = q0;     bf[np * 2][1] = q1;
                bf[np * 2 + 1][0] = q2; bf[np * 2 + 1][1] = q3;
            }
            #pragma unroll
            for (int mf = 0; mf < 4; mf++)
                #pragma unroll
                for (int nf = 0; nf < 8; nf++)
                    mma16816(acc[mf][nf], af[mf], bf[nf]);
        }

        if (kt + 4 < nkt) LOAD_TILE(ls, kt + 4);
        cp_commit();
        if (++s == STAGES) s = 0;
        if (++ls == STAGES) ls = 0;
    }
    #undef LOAD_TILE

    // epilogue
    size_t cm = (size_t)tok0 + wm * 64;
    size_t cn = (size_t)n_loc * BKN + wn * 64;
    #pragma unroll
    for (int mf = 0; mf < 4; mf++) {
        #pragma unroll
        for (int nf = 0; nf < 8; nf++) {
            size_t row = cm + mf * 16 + (lane >> 2);
            size_t col = cn + nf * 8 + (lane & 3) * 2;
            if (HALF_OUT) {
                __half* C = (__half*)Cv;
                *(__half2*)&C[row * Ntot + col] = __floats2half2_rn(acc[mf][nf][0], acc[mf][nf][1]);
                *(__half2*)&C[(row + 8) * Ntot + col] = __floats2half2_rn(acc[mf][nf][2], acc[mf][nf][3]);
            } else {
                float* C = (float*)Cv;
                *(float2*)&C[row * Ntot + col] = make_float2(acc[mf][nf][0], acc[mf][nf][1]);
                *(float2*)&C[(row + 8) * Ntot + col] = make_float2(acc[mf][nf][2], acc[mf][nf][3]);
            }
        }
    }
}

// ---------- attention over G=18 connections (fp16 in/out) ----------
// 128 threads per token: warp w owns head pair (2w, 2w+1); lanes 0-15 -> even
// head, 16-31 -> odd head; each lane owns 4 contiguous halfs (one uint2).
// No duplicated loads; 8B per lane per (j, matrix).
__global__ __launch_bounds__(128)
void attn_kernel(const uint2* __restrict__ q, const uint2* __restrict__ key,
                 const uint2* __restrict__ val, uint2* __restrict__ outh) {
    int bs = blockIdx.x;
    int hp = threadIdx.x >> 5;            // head pair 0..3
    int lane = threadIdx.x & 31;

    union U2 { uint2 u; __half2 h[2]; };

    size_t qbase = ((size_t)bs * HH + hp * 128) / 4 + lane;   // uint2 units
    U2 qv; qv.u = q[qbase];
    float2 q0 = __half22float2(qv.h[0]);
    float2 q1 = __half22float2(qv.h[1]);

    float sc[GG];
    const uint2* kb = key + ((size_t)bs * GH + hp * 128) / 4 + lane;
    #pragma unroll
    for (int j = 0; j < GG; j++) {
        U2 kv; kv.u = kb[(size_t)j * (HH / 4)];
        float2 k0 = __half22float2(kv.h[0]);
        float2 k1 = __half22float2(kv.h[1]);
        float s = q0.x * k0.x + q0.y * k0.y + q1.x * k1.x + q1.y * k1.y;
        // butterfly over each 16-lane half (masks 8,4,2,1 stay within half)
        s += __shfl_xor_sync(0xFFFFFFFFu, s, 8);
        s += __shfl_xor_sync(0xFFFFFFFFu, s, 4);
        s += __shfl_xor_sync(0xFFFFFFFFu, s, 2);
        s += __shfl_xor_sync(0xFFFFFFFFu, s, 1);
        sc[j] = s * 0.125f;   // 1/sqrt(64)
    }
    float m = sc[0];
    #pragma unroll
    for (int j = 1; j < GG; j++) m = fmaxf(m, sc[j]);
    float sum = 0.f;
    #pragma unroll
    for (int j = 0; j < GG; j++) { sc[j] = __expf(sc[j] - m); sum += sc[j]; }
    float inv = 1.f / sum;

    float o0x = 0.f, o0y = 0.f, o1x = 0.f, o1y = 0.f;
    const uint2* vb = val + ((size_t)bs * GH + hp * 128) / 4 + lane;
    #pragma unroll
    for (int j = 0; j < GG; j++) {
        U2 vv; vv.u = vb[(size_t)j * (HH / 4)];
        float2 v0 = __half22float2(vv.h[0]);
        float2 v1 = __half22float2(vv.h[1]);
        o0x = fmaf(sc[j], v0.x, o0x); o0y = fmaf(sc[j], v0.y, o0y);
        o1x = fmaf(sc[j], v1.x, o1x); o1y = fmaf(sc[j], v1.y, o1y);
    }
    U2 o;
    o.h[0] = __floats2half2_rn(o0x * inv, o0y * inv);
    o.h[1] = __floats2half2_rn(o1x * inv, o1y * inv);
    outh[qbase] = o.u;
}

// ---------- launch ----------
extern "C" void kernel_launch(void* const* d_in, const int* in_sizes, int n_in,
                              void* d_out, int out_size) {
    const float* hidden = (const float*)d_in[0];
    const void*  conn   = d_in[1];
    const float* Wq     = (const float*)d_in[2];
    const float* Wk     = (const float*)d_in[3];
    const float* Wv     = (const float*)d_in[4];
    const float* Wo     = (const float*)d_in[5];
    float* out = (float*)d_out;

    __half *pHid, *pWkh, *pWvh, *pWqh, *pWoh, *pKeyh, *pValh, *pQh, *pAttnh;
    cudaGetSymbolAddress((void**)&pHid,   g_hidh);
    cudaGetSymbolAddress((void**)&pWkh,   g_Wkh);
    cudaGetSymbolAddress((void**)&pWvh,   g_Wvh);
    cudaGetSymbolAddress((void**)&pWqh,   g_Wqh);
    cudaGetSymbolAddress((void**)&pWoh,   g_Woh);
    cudaGetSymbolAddress((void**)&pKeyh,  g_keyh);
    cudaGetSymbolAddress((void**)&pValh,  g_valh);
    cudaGetSymbolAddress((void**)&pQh,    g_qh);
    cudaGetSymbolAddress((void**)&pAttnh, g_attnh);

    cudaFuncSetAttribute((const void*)gemm_mma<true, true, true>,
                         cudaFuncAttributeMaxDynamicSharedMemorySize, SMEM_G);
    cudaFuncSetAttribute((const void*)gemm_mma<false, false, false>,
                         cudaFuncAttributeMaxDynamicSharedMemorySize, SMEM_G);

    // 1) int width detection
    detect_kernel<<<1, 32>>>((const int*)conn);

    // 2) fp16 conversion of all operands (16B stores)
    {
        size_t total = H2 + 2 * W2 + 2 * S2;
        prep_kernel<<<(unsigned)((total + 255) / 256), 256>>>(
            (const float4*)hidden, (const float4*)Wk, (const float4*)Wv,
            (const float4*)Wq, (const float4*)Wo,
            (uint4*)pHid, (uint4*)pWkh, (uint4*)pWvh, (uint4*)pWqh, (uint4*)pWoh);
    }

    // 3) key+value+query in ONE launch: n tiles span Wk|Wv|Wq
    {
        int n_tiles = KV_TILES + Q_TILES;          // 148
        int grid = (MTOK / BKM) * n_tiles;         // 9472
        gemm_mma<true, true, true><<<grid, NTHR, SMEM_G>>>(
            pHid, pWkh, pWvh, pWqh, pKeyh, pValh, pQh, conn,
            GH, GH, n_tiles, GH / BKN, KV_TILES, GH / BKK, HH, HH / BKK);
    }

    // 4) attention (fp16 in/out, 8B loads, no duplication)
    attn_kernel<<<MTOK, 128>>>((const uint2*)pQh, (const uint2*)pKeyh,
                               (const uint2*)pValh, (uint2*)pAttnh);

    // 5) out = attn @ Wo -> fp32
    gemm_mma<false, false, false><<<(MTOK / BKM) * (HH / BKN), NTHR, SMEM_G>>>(
        pAttnh, pWoh, pWoh, pWoh, out, out, out, nullptr,
        HH, HH, HH / BKN, HH / BKN, HH / BKN, HH / BKK, HH, HH / BKK);
}